// round 1
// baseline (speedup 1.0000x reference)
#include <cuda_runtime.h>
#include <cuda_bf16.h>

#define NNODES 100000
#define NEDGES 800000
#define ETOT   900000
#define MAXHC  240
#define MAXH   10
#define NEG_SLOPE 0.2f

// ---------------- scratch (device globals; no allocation allowed) ----------------
__device__ float g_h   [NNODES * MAXHC];   // h = act(x) @ W
__device__ float g_buf0[NNODES * MAXHC];   // layer outputs (ping)
__device__ float g_buf1[NNODES * MAXHC];   // layer outputs (pong)
__device__ float g_as  [NNODES * MAXH];    // alpha_src per node/head
__device__ float g_ad  [NNODES * MAXH];    // alpha_dst per node/head
__device__ int   g_m   [NNODES * MAXH];    // segment max (monotone int encoding)
__device__ float g_z   [NNODES * MAXH];    // segment sum of exp
__device__ float g_e   [ETOT   * MAXH];    // per-edge logits -> exp values

// ---------------- helpers ----------------
__device__ __forceinline__ void atomic_max_float(int* addr, float v) {
    // monotone encoding: int-max for v>=0, unsigned-min for v<0. init = 0xff800000 (-inf)
    if (v >= 0.0f) atomicMax(addr, __float_as_int(v));
    else           atomicMin((unsigned int*)addr, (unsigned int)__float_as_int(v));
}

__device__ __forceinline__ void red_add_v4(float* addr, float4 v) {
    asm volatile("red.global.add.v4.f32 [%0], {%1,%2,%3,%4};"
                 :: "l"(addr), "f"(v.x), "f"(v.y), "f"(v.z), "f"(v.w) : "memory");
}

// ---------------- init: zero out-buffer, m=-inf, z=0 ----------------
__global__ __launch_bounds__(256) void init_kernel(float* out, int* m, float* z,
                                                   int n_out, int n_mz) {
    int i = blockIdx.x * blockDim.x + threadIdx.x;
    if (i < n_out) out[i] = 0.0f;
    if (i < n_mz) { m[i] = (int)0xff800000; z[i] = 0.0f; }
}

// ---------------- SGEMM: out[M,N] = act(A)[M,K] @ W[K,N] ----------------
// act(a) = bias ? max(a + bias[k], 0) : a   (fused ReLU+bias of previous layer)
// BM=128, BN=64, BK=8, 256 threads, thread tile 8x4. K % 8 == 0 always here.
__global__ __launch_bounds__(256) void gemm_act_kernel(
    const float* __restrict__ A, const float* __restrict__ W,
    const float* __restrict__ bias, float* __restrict__ out,
    int M, int K, int N)
{
    __shared__ float As[8][128];
    __shared__ float Bs[8][64];

    const int tid  = threadIdx.x;
    const int row0 = blockIdx.y * 128;
    const int col0 = blockIdx.x * 64;

    const int ty = tid >> 4;        // 0..15 -> 8 rows each
    const int tx = tid & 15;        // 0..15 -> 4 cols each

    const int arow = tid >> 1;              // 0..127
    const int acol = (tid & 1) * 4;         // 0 or 4
    const int brow = tid >> 5;               // 0..7
    const int bcol = (tid & 31) * 2;        // 0..62

    float acc[8][4];
#pragma unroll
    for (int i = 0; i < 8; i++)
#pragma unroll
        for (int j = 0; j < 4; j++) acc[i][j] = 0.0f;

    for (int k0 = 0; k0 < K; k0 += 8) {
        // --- load A tile (with fused bias+relu) ---
        float4 av = make_float4(0.f, 0.f, 0.f, 0.f);
        int gr = row0 + arow;
        if (gr < M) {
            av = *(const float4*)(A + (long)gr * K + k0 + acol);
            if (bias) {
                av.x = fmaxf(av.x + __ldg(bias + k0 + acol + 0), 0.f);
                av.y = fmaxf(av.y + __ldg(bias + k0 + acol + 1), 0.f);
                av.z = fmaxf(av.z + __ldg(bias + k0 + acol + 2), 0.f);
                av.w = fmaxf(av.w + __ldg(bias + k0 + acol + 3), 0.f);
            }
        }
        As[acol + 0][arow] = av.x;
        As[acol + 1][arow] = av.y;
        As[acol + 2][arow] = av.z;
        As[acol + 3][arow] = av.w;

        // --- load W tile ---
        float2 bv = make_float2(0.f, 0.f);
        int gc = col0 + bcol;
        if (gc + 1 < N)      bv = *(const float2*)(W + (long)(k0 + brow) * N + gc);
        else if (gc < N)     bv.x = W[(long)(k0 + brow) * N + gc];
        Bs[brow][bcol]     = bv.x;
        Bs[brow][bcol + 1] = bv.y;

        __syncthreads();

#pragma unroll
        for (int k = 0; k < 8; k++) {
            float a[8], b[4];
#pragma unroll
            for (int i = 0; i < 8; i++) a[i] = As[k][ty * 8 + i];
#pragma unroll
            for (int j = 0; j < 4; j++) b[j] = Bs[k][tx * 4 + j];
#pragma unroll
            for (int i = 0; i < 8; i++)
#pragma unroll
                for (int j = 0; j < 4; j++) acc[i][j] += a[i] * b[j];
        }
        __syncthreads();
    }

#pragma unroll
    for (int i = 0; i < 8; i++) {
        int r = row0 + ty * 8 + i;
        if (r >= M) continue;
#pragma unroll
        for (int j = 0; j < 4; j++) {
            int c = col0 + tx * 4 + j;
            if (c < N) out[(long)r * N + c] = acc[i][j];
        }
    }
}

// ---------------- alpha: alpha_s[n,h] = sum_c h[n,h,c]*a_src[h,c] ----------------
__global__ __launch_bounds__(256) void alpha_kernel(
    const float* __restrict__ h, const float* __restrict__ a_s,
    const float* __restrict__ a_d, float* __restrict__ alpha_s,
    float* __restrict__ alpha_d, int H, int C)
{
    int idx = blockIdx.x * blockDim.x + threadIdx.x;
    if (idx >= NNODES * H) return;
    int node = idx / H;
    int hh   = idx - node * H;
    const float* hp = h + (long)node * H * C + hh * C;
    float ss = 0.f, sd = 0.f;
    for (int c = 0; c < C; c++) {
        float v = hp[c];
        ss += v * __ldg(a_s + hh * C + c);
        sd += v * __ldg(a_d + hh * C + c);
    }
    alpha_s[idx] = ss;
    alpha_d[idx] = sd;
}

// ---------------- edge pass 1: e = leakyrelu(as[src]+ad[dst]); segment max ----------------
__global__ __launch_bounds__(256) void edge_pass1(
    const int* __restrict__ ei, const float* __restrict__ as,
    const float* __restrict__ ad, float* __restrict__ ebuf,
    int* __restrict__ m, int H)
{
    int idx = blockIdx.x * blockDim.x + threadIdx.x;
    if (idx >= ETOT * H) return;
    int e  = idx / H;
    int hh = idx - e * H;
    int s, d;
    if (e < NEDGES) { s = __ldg(ei + e); d = __ldg(ei + NEDGES + e); }
    else            { s = e - NEDGES; d = s; }
    float v = __ldg(as + s * H + hh) + __ldg(ad + d * H + hh);
    v = (v > 0.f) ? v : NEG_SLOPE * v;
    ebuf[idx] = v;
    atomic_max_float(&m[d * H + hh], v);
}

// ---------------- edge pass 2: ex = exp(e - m[dst]); segment sum ----------------
__global__ __launch_bounds__(256) void edge_pass2(
    const int* __restrict__ ei, float* __restrict__ ebuf,
    const int* __restrict__ m, float* __restrict__ z, int H)
{
    int idx = blockIdx.x * blockDim.x + threadIdx.x;
    if (idx >= ETOT * H) return;
    int e  = idx / H;
    int hh = idx - e * H;
    int d;
    if (e < NEDGES) d = __ldg(ei + NEDGES + e);
    else            d = e - NEDGES;
    float mm = __int_as_float(__ldg(m + d * H + hh));
    float ex = __expf(ebuf[idx] - mm);
    ebuf[idx] = ex;
    atomicAdd(&z[d * H + hh], ex);
}

// ---------------- edge pass 3: out[dst] += (ex/z[dst]) * h[src] (vec4 reductions) ----------------
__global__ __launch_bounds__(256) void edge_scatter(
    const int* __restrict__ ei, const float* __restrict__ ex,
    const float* __restrict__ z, const float* __restrict__ h,
    float* __restrict__ out, int H, int C, int HC, int nchunks)
{
    long idx = (long)blockIdx.x * blockDim.x + threadIdx.x;
    long total = (long)ETOT * nchunks;
    if (idx >= total) return;
    int e = (int)(idx / nchunks);
    int q = (int)(idx - (long)e * nchunks);
    int s, d;
    if (e < NEDGES) { s = __ldg(ei + e); d = __ldg(ei + NEDGES + e); }
    else            { s = e - NEDGES; d = s; }
    int head = (q * 4) / C;
    float attn = __ldg(ex + (long)e * H + head) / __ldg(z + (long)d * H + head);
    float4 hv = *(const float4*)(h + (long)s * HC + q * 4);
    float4 v = make_float4(hv.x * attn, hv.y * attn, hv.z * attn, hv.w * attn);
    red_add_v4(out + (long)d * HC + q * 4, v);
}

// ---------------- epilogue: final relu(out + b) -> d_out ----------------
__global__ __launch_bounds__(256) void epilogue_kernel(
    const float* __restrict__ in, const float* __restrict__ bias,
    float* __restrict__ out, int n, int width)
{
    int i = blockIdx.x * blockDim.x + threadIdx.x;
    if (i >= n) return;
    out[i] = fmaxf(in[i] + __ldg(bias + (i % width)), 0.f);
}

// ---------------- host orchestration ----------------
extern "C" void kernel_launch(void* const* d_in, const int* in_sizes, int n_in,
                              void* d_out, int out_size)
{
    const float* x  = (const float*)d_in[0];
    const int*   ei = (const int*)d_in[1];
    // d_in[2] = edge_attr (unused by reference)

    float *h, *buf0, *buf1, *as, *ad, *z, *ebuf;
    int* m;
    {
        void* p;
        cudaGetSymbolAddress(&p, g_h);    h    = (float*)p;
        cudaGetSymbolAddress(&p, g_buf0); buf0 = (float*)p;
        cudaGetSymbolAddress(&p, g_buf1); buf1 = (float*)p;
        cudaGetSymbolAddress(&p, g_as);   as   = (float*)p;
        cudaGetSymbolAddress(&p, g_ad);   ad   = (float*)p;
        cudaGetSymbolAddress(&p, g_m);    m    = (int*)p;
        cudaGetSymbolAddress(&p, g_z);    z    = (float*)p;
        cudaGetSymbolAddress(&p, g_e);    ebuf = (float*)p;
    }

    const int DINS[5] = {32, 240, 120, 48, 24};
    const int CS[5]   = {24, 24, 24, 24, 12};
    const int HS[5]   = {10, 5, 2, 1, 1};

    const float* cur_in   = x;
    const float* cur_bias = nullptr;

    for (int i = 0; i < 5; i++) {
        int din = DINS[i], C = CS[i], H = HS[i], HC = H * C;
        const float* W   = (const float*)d_in[3 + 4 * i];
        const float* b   = (const float*)d_in[4 + 4 * i];
        const float* a_s = (const float*)d_in[5 + 4 * i];
        const float* a_d = (const float*)d_in[6 + 4 * i];
        float* outb = (i % 2 == 0) ? buf0 : buf1;

        // init out buffer + m/z
        {
            int n_out = NNODES * HC, n_mz = NNODES * H;
            int n = (n_out > n_mz) ? n_out : n_mz;
            init_kernel<<<(n + 255) / 256, 256>>>(outb, m, z, n_out, n_mz);
        }

        // GEMM with fused bias+relu of previous layer on the A operand
        {
            dim3 grid((HC + 63) / 64, (NNODES + 127) / 128);
            gemm_act_kernel<<<grid, 256>>>(cur_in, W, cur_bias, h, NNODES, din, HC);
        }

        // alpha
        {
            int n = NNODES * H;
            alpha_kernel<<<(n + 255) / 256, 256>>>(h, a_s, a_d, as, ad, H, C);
        }

        // edge passes
        {
            int n = ETOT * H;
            edge_pass1<<<(n + 255) / 256, 256>>>(ei, as, ad, ebuf, m, H);
            edge_pass2<<<(n + 255) / 256, 256>>>(ei, ebuf, m, z, H);
        }
        {
            int nchunks = HC / 4;
            long total = (long)ETOT * nchunks;
            int blocks = (int)((total + 255) / 256);
            edge_scatter<<<blocks, 256>>>(ei, ebuf, z, h, outb, H, C, HC, nchunks);
        }

        cur_in = outb;
        cur_bias = b;
    }

    // final relu(out + b4) -> d_out (100000 x 12 f32)
    {
        int n = NNODES * 12;
        epilogue_kernel<<<(n + 255) / 256, 256>>>(cur_in, cur_bias, (float*)d_out, n, 12);
    }
}

// round 2
// speedup vs baseline: 1.1426x; 1.1426x over previous
#include <cuda_runtime.h>
#include <cuda_bf16.h>

#define NNODES 100000
#define NEDGES 800000
#define ETOT   900000
#define MAXHC  240
#define MAXH   10
#define NEG_SLOPE 0.2f
#define MAXBLK 4096   // >= ceil(NNODES*MAXH/256) = 3907

// ---------------- scratch (device globals; no allocation allowed) ----------------
__device__ float    g_h   [NNODES * MAXHC];   // h = act(x) @ W
__device__ float    g_buf0[NNODES * MAXHC];   // layer outputs (ping)
__device__ float    g_buf1[NNODES * MAXHC];   // layer outputs (pong)
__device__ float    g_as  [NNODES * MAXH];    // alpha_src per node/head
__device__ float    g_ad  [NNODES * MAXH];    // alpha_dst per node/head
__device__ float    g_z   [NNODES * MAXH];    // segment sum of exp
__device__ float    g_e   [ETOT   * MAXH];    // per-edge exp -> attn values
__device__ unsigned g_part[MAXBLK * MAXH];    // per-block encoded max partials
__device__ float    g_smax[MAXH];             // per-head global max of alpha_s

// ---------------- helpers ----------------
// order-preserving float->unsigned encoding (for max via unsigned atomicMax)
__device__ __forceinline__ unsigned enc_f(float v) {
    unsigned u = __float_as_uint(v);
    return (u & 0x80000000u) ? ~u : (u | 0x80000000u);
}
__device__ __forceinline__ float dec_f(unsigned u) {
    return __uint_as_float((u & 0x80000000u) ? (u ^ 0x80000000u) : ~u);
}

__device__ __forceinline__ void red_add_v4(float* addr, float4 v) {
    asm volatile("red.global.add.v4.f32 [%0], {%1,%2,%3,%4};"
                 :: "l"(addr), "f"(v.x), "f"(v.y), "f"(v.z), "f"(v.w) : "memory");
}

#define PACK2(out, lo, hi) \
    asm("mov.b64 %0, {%1, %2};" : "=l"(out) : "r"(__float_as_uint(lo)), "r"(__float_as_uint(hi)))
#define FMA2(d, a, b) \
    asm("fma.rn.f32x2 %0, %1, %2, %0;" : "+l"(d) : "l"(a), "l"(b))
#define UNPACK2(lo, hi, in) \
    asm("mov.b64 {%0, %1}, %2;" : "=r"(lo), "=r"(hi) : "l"(in))

// ---------------- init: zero out-buffer and z ----------------
__global__ __launch_bounds__(256) void init_kernel(float* out, float* z,
                                                   int n_out, int n_z) {
    int i = blockIdx.x * blockDim.x + threadIdx.x;
    if (i < n_out) out[i] = 0.0f;
    if (i < n_z)   z[i]   = 0.0f;
}

// ---------------- SGEMM with packed f32x2 FMAs ----------------
// out[M,N] = act(A)[M,K] @ W[K,N];  act = bias? relu(a+bias[k]) : a
// BM=128, BN=64, BK=8, 256 threads, thread tile 8 rows x 4 cols (4 row-pairs).
__global__ __launch_bounds__(256) void gemm_act_kernel(
    const float* __restrict__ A, const float* __restrict__ W,
    const float* __restrict__ bias, float* __restrict__ out,
    int M, int K, int N)
{
    __shared__ float As[8][128];
    __shared__ float Bs[8][64];

    const int tid  = threadIdx.x;
    const int row0 = blockIdx.y * 128;
    const int col0 = blockIdx.x * 64;

    const int ty = tid >> 4;        // 0..15 -> 8 rows each
    const int tx = tid & 15;        // 0..15 -> 4 cols each

    const int arow = tid >> 1;              // 0..127
    const int acol = (tid & 1) * 4;         // 0 or 4
    const int brow = tid >> 5;              // 0..7
    const int bcol = (tid & 31) * 2;        // 0..62

    unsigned long long acc[4][4];           // [row-pair][col], each = 2 fp32 rows
#pragma unroll
    for (int i = 0; i < 4; i++)
#pragma unroll
        for (int j = 0; j < 4; j++) acc[i][j] = 0ULL;

    for (int k0 = 0; k0 < K; k0 += 8) {
        // --- load A tile (fused bias+relu of previous layer) ---
        float4 av = make_float4(0.f, 0.f, 0.f, 0.f);
        int gr = row0 + arow;
        if (gr < M) {
            av = *(const float4*)(A + (long)gr * K + k0 + acol);
            if (bias) {
                av.x = fmaxf(av.x + __ldg(bias + k0 + acol + 0), 0.f);
                av.y = fmaxf(av.y + __ldg(bias + k0 + acol + 1), 0.f);
                av.z = fmaxf(av.z + __ldg(bias + k0 + acol + 2), 0.f);
                av.w = fmaxf(av.w + __ldg(bias + k0 + acol + 3), 0.f);
            }
        }
        As[acol + 0][arow] = av.x;
        As[acol + 1][arow] = av.y;
        As[acol + 2][arow] = av.z;
        As[acol + 3][arow] = av.w;

        // --- load W tile ---
        float2 bv = make_float2(0.f, 0.f);
        int gc = col0 + bcol;
        if (gc + 1 < N)      bv = *(const float2*)(W + (long)(k0 + brow) * N + gc);
        else if (gc < N)     bv.x = W[(long)(k0 + brow) * N + gc];
        Bs[brow][bcol]     = bv.x;
        Bs[brow][bcol + 1] = bv.y;

        __syncthreads();

#pragma unroll
        for (int k = 0; k < 8; k++) {
            // A row-pairs loaded directly as 64-bit (adjacent rows in As row)
            const unsigned long long* ap =
                (const unsigned long long*)&As[k][ty * 8];
            unsigned long long a01 = ap[0], a23 = ap[1], a45 = ap[2], a67 = ap[3];
            const float4 b4 = *(const float4*)&Bs[k][tx * 4];
            unsigned long long bb[4];
            PACK2(bb[0], b4.x, b4.x);
            PACK2(bb[1], b4.y, b4.y);
            PACK2(bb[2], b4.z, b4.z);
            PACK2(bb[3], b4.w, b4.w);
#pragma unroll
            for (int j = 0; j < 4; j++) {
                FMA2(acc[0][j], a01, bb[j]);
                FMA2(acc[1][j], a23, bb[j]);
                FMA2(acc[2][j], a45, bb[j]);
                FMA2(acc[3][j], a67, bb[j]);
            }
        }
        __syncthreads();
    }

#pragma unroll
    for (int i = 0; i < 4; i++) {
        int r0r = row0 + ty * 8 + 2 * i;
#pragma unroll
        for (int j = 0; j < 4; j++) {
            int c = col0 + tx * 4 + j;
            unsigned lo, hi;
            UNPACK2(lo, hi, acc[i][j]);
            if (c < N) {
                if (r0r     < M) out[(long)(r0r)     * N + c] = __uint_as_float(lo);
                if (r0r + 1 < M) out[(long)(r0r + 1) * N + c] = __uint_as_float(hi);
            }
        }
    }
}

// ---------------- alpha + per-block partial max of alpha_s ----------------
__global__ __launch_bounds__(256) void alpha_kernel(
    const float* __restrict__ h, const float* __restrict__ a_s,
    const float* __restrict__ a_d, float* __restrict__ alpha_s,
    float* __restrict__ alpha_d, unsigned* __restrict__ part,
    int H, int C)
{
    __shared__ unsigned s_max[MAXH];
    if (threadIdx.x < H) s_max[threadIdx.x] = 0u;   // 0 = encoded minimum
    __syncthreads();

    int idx = blockIdx.x * blockDim.x + threadIdx.x;
    int hh = 0;
    if (idx < NNODES * H) {
        int node = idx / H;
        hh = idx - node * H;
        const float4* hp = (const float4*)(h + (long)node * H * C + hh * C);
        const float4* asp = (const float4*)(a_s + hh * C);
        const float4* adp = (const float4*)(a_d + hh * C);
        float ss = 0.f, sd = 0.f;
        int c4 = C >> 2;
        for (int c = 0; c < c4; c++) {
            float4 v = hp[c];
            float4 s4 = __ldg(asp + c);
            float4 d4 = __ldg(adp + c);
            ss += v.x * s4.x + v.y * s4.y + v.z * s4.z + v.w * s4.w;
            sd += v.x * d4.x + v.y * d4.y + v.z * d4.z + v.w * d4.w;
        }
        alpha_s[idx] = ss;
        alpha_d[idx] = sd;
        atomicMax(&s_max[hh], enc_f(ss));
    }
    __syncthreads();
    if (threadIdx.x < H)
        part[blockIdx.x * H + threadIdx.x] = s_max[threadIdx.x];
}

// ---------------- final per-head max reduce ----------------
__global__ __launch_bounds__(256) void smax_reduce_kernel(
    const unsigned* __restrict__ part, float* __restrict__ smax,
    int nblocks, int H)
{
    __shared__ unsigned sh[256];
    int h = blockIdx.x;
    unsigned best = 0u;
    for (int i = threadIdx.x; i < nblocks; i += 256)
        best = max(best, part[i * H + h]);
    sh[threadIdx.x] = best;
    __syncthreads();
    for (int s = 128; s > 0; s >>= 1) {
        if (threadIdx.x < s) sh[threadIdx.x] = max(sh[threadIdx.x], sh[threadIdx.x + s]);
        __syncthreads();
    }
    if (threadIdx.x == 0) smax[h] = dec_f(sh[0]);
}

// ---------------- fused edge pass: e, exp(e - m_ub), segment-sum z ----------------
// m_ub[d,h] = leakyrelu(smax[h] + ad[d,h]) >= leakyrelu(as[s,h] + ad[d,h]) for all s
// (leakyrelu monotone, smax >= as). Softmax is shift-invariant -> exact result.
__global__ __launch_bounds__(256) void edge_fused(
    const int* __restrict__ ei, const float* __restrict__ as,
    const float* __restrict__ ad, const float* __restrict__ smax,
    float* __restrict__ ebuf, float* __restrict__ z, int H)
{
    int idx = blockIdx.x * blockDim.x + threadIdx.x;
    if (idx >= ETOT * H) return;
    int e  = idx / H;
    int hh = idx - e * H;
    int s, d;
    if (e < NEDGES) { s = __ldg(ei + e); d = __ldg(ei + NEDGES + e); }
    else            { s = e - NEDGES; d = s; }
    float asv = __ldg(as + s * H + hh);
    float adv = __ldg(ad + d * H + hh);
    float ev = asv + adv;
    ev = (ev > 0.f) ? ev : NEG_SLOPE * ev;
    float mb = __ldg(smax + hh) + adv;
    mb = (mb > 0.f) ? mb : NEG_SLOPE * mb;
    float ex = __expf(ev - mb);
    ebuf[idx] = ex;
    atomicAdd(&z[d * H + hh], ex);
}

// ---------------- normalize: attn = ex / z[dst] (in-place) ----------------
__global__ __launch_bounds__(256) void attn_norm(
    const int* __restrict__ ei, float* __restrict__ ebuf,
    const float* __restrict__ z, int H)
{
    int idx = blockIdx.x * blockDim.x + threadIdx.x;
    if (idx >= ETOT * H) return;
    int e  = idx / H;
    int hh = idx - e * H;
    int d;
    if (e < NEDGES) d = __ldg(ei + NEDGES + e);
    else            d = e - NEDGES;
    ebuf[idx] = ebuf[idx] / __ldg(z + d * H + hh);
}

// ---------------- scatter: out[dst] += attn * h[src] (vec4 reductions) ----------------
__global__ __launch_bounds__(256) void edge_scatter(
    const int* __restrict__ ei, const float* __restrict__ attn,
    const float* __restrict__ h, float* __restrict__ out,
    int H, int cpH /* (C/4) chunks per head */, int HC, int nchunks)
{
    long idx = (long)blockIdx.x * blockDim.x + threadIdx.x;
    long total = (long)ETOT * nchunks;
    if (idx >= total) return;
    int e = (int)(idx / nchunks);
    int q = (int)(idx - (long)e * nchunks);
    int s, d;
    if (e < NEDGES) { s = __ldg(ei + e); d = __ldg(ei + NEDGES + e); }
    else            { s = e - NEDGES; d = s; }
    int head = q / cpH;
    float a = __ldg(attn + (long)e * H + head);
    float4 hv = *(const float4*)(h + (long)s * HC + q * 4);
    float4 v = make_float4(hv.x * a, hv.y * a, hv.z * a, hv.w * a);
    red_add_v4(out + (long)d * HC + q * 4, v);
}

// ---------------- epilogue: final relu(out + b) -> d_out ----------------
__global__ __launch_bounds__(256) void epilogue_kernel(
    const float* __restrict__ in, const float* __restrict__ bias,
    float* __restrict__ out, int n, int width)
{
    int i = blockIdx.x * blockDim.x + threadIdx.x;
    if (i >= n) return;
    out[i] = fmaxf(in[i] + __ldg(bias + (i % width)), 0.f);
}

// ---------------- host orchestration ----------------
extern "C" void kernel_launch(void* const* d_in, const int* in_sizes, int n_in,
                              void* d_out, int out_size)
{
    const float* x  = (const float*)d_in[0];
    const int*   ei = (const int*)d_in[1];
    // d_in[2] = edge_attr (unused by reference)

    float *h, *buf0, *buf1, *as, *ad, *z, *ebuf, *smax;
    unsigned* part;
    {
        void* p;
        cudaGetSymbolAddress(&p, g_h);    h    = (float*)p;
        cudaGetSymbolAddress(&p, g_buf0); buf0 = (float*)p;
        cudaGetSymbolAddress(&p, g_buf1); buf1 = (float*)p;
        cudaGetSymbolAddress(&p, g_as);   as   = (float*)p;
        cudaGetSymbolAddress(&p, g_ad);   ad   = (float*)p;
        cudaGetSymbolAddress(&p, g_z);    z    = (float*)p;
        cudaGetSymbolAddress(&p, g_e);    ebuf = (float*)p;
        cudaGetSymbolAddress(&p, g_part); part = (unsigned*)p;
        cudaGetSymbolAddress(&p, g_smax); smax = (float*)p;
    }

    const int DINS[5] = {32, 240, 120, 48, 24};
    const int CS[5]   = {24, 24, 24, 24, 12};
    const int HS[5]   = {10, 5, 2, 1, 1};

    const float* cur_in   = x;
    const float* cur_bias = nullptr;

    for (int i = 0; i < 5; i++) {
        int din = DINS[i], C = CS[i], H = HS[i], HC = H * C;
        const float* W   = (const float*)d_in[3 + 4 * i];
        const float* b   = (const float*)d_in[4 + 4 * i];
        const float* a_s = (const float*)d_in[5 + 4 * i];
        const float* a_d = (const float*)d_in[6 + 4 * i];
        float* outb = (i % 2 == 0) ? buf0 : buf1;

        // init out buffer + z
        {
            int n_out = NNODES * HC, n_z = NNODES * H;
            int n = (n_out > n_z) ? n_out : n_z;
            init_kernel<<<(n + 255) / 256, 256>>>(outb, z, n_out, n_z);
        }

        // GEMM with fused bias+relu of previous layer on the A operand
        {
            dim3 grid((HC + 63) / 64, (NNODES + 127) / 128);
            gemm_act_kernel<<<grid, 256>>>(cur_in, W, cur_bias, h, NNODES, din, HC);
        }

        // alpha + partial per-head max, then final reduce
        {
            int n = NNODES * H;
            int nblocks = (n + 255) / 256;
            alpha_kernel<<<nblocks, 256>>>(h, a_s, a_d, as, ad, part, H, C);
            smax_reduce_kernel<<<H, 256>>>(part, smax, nblocks, H);
        }

        // fused edge pass (logit + exp + segment-sum), then normalize
        {
            int n = ETOT * H;
            edge_fused<<<(n + 255) / 256, 256>>>(ei, as, ad, smax, ebuf, z, H);
            attn_norm<<<(n + 255) / 256, 256>>>(ei, ebuf, z, H);
        }

        // weighted scatter
        {
            int nchunks = HC / 4;
            long total = (long)ETOT * nchunks;
            int blocks = (int)((total + 255) / 256);
            edge_scatter<<<blocks, 256>>>(ei, ebuf, h, outb, H, C / 4, HC, nchunks);
        }

        cur_in = outb;
        cur_bias = b;
    }

    // final relu(out + b4) -> d_out (100000 x 12 f32)
    {
        int n = NNODES * 12;
        epilogue_kernel<<<(n + 255) / 256, 256>>>(cur_in, cur_bias, (float*)d_out, n, 12);
    }
}